// round 1
// baseline (speedup 1.0000x reference)
#include <cuda_runtime.h>
#include <math.h>

#define B_ 4
#define A_ 16
#define N_ 8
#define L_ 512
#define DE_ 256
#define DH_ 64
#define H_ 8
#define DHEAD_ 32
#define NL_ 4096
#define LN_EPS 1e-5f

// Scratch (no cudaMalloc allowed)
__device__ __align__(16) float g_q[B_*A_*DE_];          // 16K
__device__ __align__(16) float g_qWw[B_*A_*H_*DE_];     // 128K
__device__ float g_S0[B_*A_*H_];
__device__ float g_S1[B_*A_*H_];
__device__ __align__(16) float g_m[B_*H_*A_*DH_];       // 32K

// ---------------------------------------------------------------- K0: zero
__global__ void k0_zero(float* __restrict__ out) {
    int i = blockIdx.x * blockDim.x + threadIdx.x;
    if (i < 256) out[i] = 0.f;
    if (i < B_*H_*A_*DH_) g_m[i] = 0.f;
}

// ---------------------------------------------------------------- K1: q = LN(curr) @ Wq.T
__global__ void __launch_bounds__(256) k1_q(
    const float* __restrict__ curr, const float* __restrict__ Wq,
    const float* __restrict__ lw, const float* __restrict__ lb)
{
    int ba = blockIdx.x;          // 0..63 = b*16+a
    int t  = threadIdx.x;         // 256
    __shared__ __align__(16) float xs[DE_];
    __shared__ float red[256];

    float x = curr[ba*DE_ + t];
    red[t] = x; __syncthreads();
    for (int s = 128; s > 0; s >>= 1) { if (t < s) red[t] += red[t+s]; __syncthreads(); }
    float mu = red[0] * (1.f/DE_);
    __syncthreads();
    red[t] = (x-mu)*(x-mu); __syncthreads();
    for (int s = 128; s > 0; s >>= 1) { if (t < s) red[t] += red[t+s]; __syncthreads(); }
    float rsd = rsqrtf(red[0] * (1.f/DE_) + LN_EPS);
    __syncthreads();
    xs[t] = (x - mu) * rsd * lw[t] + lb[t];
    __syncthreads();

    float acc = 0.f;
    const float* wr = Wq + t*DE_;
    #pragma unroll 8
    for (int i = 0; i < DE_; i += 4) {
        float4 xv = *(const float4*)(xs + i);
        float4 wv = *(const float4*)(wr + i);
        acc += xv.x*wv.x + xv.y*wv.y + xv.z*wv.z + xv.w*wv.w;
    }
    g_q[ba*DE_ + t] = acc;
}

// ---------------------------------------------------------------- K2: qWw, S0, S1
__global__ void __launch_bounds__(256) k2_qw(
    const float* __restrict__ Wk, const float* __restrict__ lkw,
    const float* __restrict__ lkb)
{
    int bah = blockIdx.x;         // (b*16+a)*8 + h
    int h   = bah & 7;
    int ba  = bah >> 3;
    int t   = threadIdx.x;
    __shared__ float qs[DHEAD_];
    __shared__ float red[256];

    if (t < DHEAD_) qs[t] = g_q[ba*DE_ + h*DHEAD_ + t];
    __syncthreads();

    float acc = 0.f;
    #pragma unroll
    for (int d = 0; d < DHEAD_; d++)
        acc += qs[d] * Wk[(h*DHEAD_ + d)*DE_ + t];

    const float sc = 0.1767766952966369f;   // 1/sqrt(32)
    float qww = acc * lkw[t] * sc;
    float s0c = acc * lkb[t] * sc;
    g_qWw[bah*DE_ + t] = qww;

    red[t] = qww; __syncthreads();
    for (int s = 128; s > 0; s >>= 1) { if (t < s) red[t] += red[t+s]; __syncthreads(); }
    if (t == 0) g_S1[bah] = red[0];
    __syncthreads();
    red[t] = s0c; __syncthreads();
    for (int s = 128; s > 0; s >>= 1) { if (t < s) red[t] += red[t+s]; __syncthreads(); }
    if (t == 0) g_S0[bah] = red[0];
}

// ---------------------------------------------------------------- K3: fused LN+proj scores
// warp per (b,n,l,a) row; qWw coefficients live in registers.
__global__ void __launch_bounds__(256) k3_scores(
    const float* __restrict__ demo, const int* __restrict__ mask,
    float* __restrict__ attn)
{
    int ba    = blockIdx.y;               // 64
    int chunk = blockIdx.x;               // 16 chunks of 256 rows
    int b = ba >> 4, a = ba & 15;
    int w    = threadIdx.x >> 5;
    int lane = threadIdx.x & 31;

    // per-lane coefficient slice: i in {lane*4..+3} U {128+lane*4..+3}
    float4 c0[H_], c1[H_];
    const float4* qw4 = (const float4*)(g_qWw + ba*H_*DE_);
    #pragma unroll
    for (int h = 0; h < H_; h++) {
        c0[h] = qw4[h*64 + lane];
        c1[h] = qw4[h*64 + 32 + lane];
    }
    float S1v[H_], S0v[H_];
    #pragma unroll
    for (int h = 0; h < H_; h++) { S1v[h] = g_S1[ba*H_+h]; S0v[h] = g_S0[ba*H_+h]; }

    for (int j = 0; j < 32; j++) {
        int x = chunk*256 + w*32 + j;
        const float4* xp = (const float4*)(demo + (size_t)(b*NL_ + x)*(A_*DE_) + a*DE_);
        float4 x0 = xp[lane];
        float4 x1 = xp[32 + lane];

        float sum = x0.x + x0.y + x0.z + x0.w + x1.x + x1.y + x1.z + x1.w;
        float ssq = x0.x*x0.x + x0.y*x0.y + x0.z*x0.z + x0.w*x0.w
                  + x1.x*x1.x + x1.y*x1.y + x1.z*x1.z + x1.w*x1.w;
        float dot[H_];
        #pragma unroll
        for (int h = 0; h < H_; h++) {
            dot[h] = c0[h].x*x0.x + c0[h].y*x0.y + c0[h].z*x0.z + c0[h].w*x0.w
                   + c1[h].x*x1.x + c1[h].y*x1.y + c1[h].z*x1.z + c1[h].w*x1.w;
        }
        #pragma unroll
        for (int off = 16; off > 0; off >>= 1) {
            sum += __shfl_xor_sync(0xffffffffu, sum, off);
            ssq += __shfl_xor_sync(0xffffffffu, ssq, off);
            #pragma unroll
            for (int h = 0; h < H_; h++)
                dot[h] += __shfl_xor_sync(0xffffffffu, dot[h], off);
        }
        float mu  = sum * (1.f/256.f);
        float var = ssq * (1.f/256.f) - mu*mu;
        float rsd = rsqrtf(var + LN_EPS);
        int   mk  = mask[b*NL_ + x];
        #pragma unroll
        for (int h = 0; h < H_; h++) {
            float sc = (dot[h] - mu*S1v[h]) * rsd + S0v[h];
            if (lane == h)
                attn[((size_t)(b*H_+h)*A_ + a)*NL_ + x] = mk ? sc : -INFINITY;
        }
    }
}

// ---------------------------------------------------------------- K4: softmax in-place over NL
__global__ void __launch_bounds__(256) k4_softmax(float* __restrict__ attn)
{
    int row = blockIdx.x;                 // 512 = b*H*A
    float4* p = (float4*)(attn + (size_t)row*NL_);
    int t = threadIdx.x;
    __shared__ float red[256];

    float4 v[4];
    float mx = -INFINITY;
    #pragma unroll
    for (int k = 0; k < 4; k++) {
        v[k] = p[t + 256*k];
        mx = fmaxf(mx, fmaxf(fmaxf(v[k].x, v[k].y), fmaxf(v[k].z, v[k].w)));
    }
    red[t] = mx; __syncthreads();
    for (int s = 128; s > 0; s >>= 1) { if (t < s) red[t] = fmaxf(red[t], red[t+s]); __syncthreads(); }
    mx = red[0]; __syncthreads();

    float sum = 0.f;
    #pragma unroll
    for (int k = 0; k < 4; k++) {
        v[k].x = __expf(v[k].x - mx); v[k].y = __expf(v[k].y - mx);
        v[k].z = __expf(v[k].z - mx); v[k].w = __expf(v[k].w - mx);
        sum += v[k].x + v[k].y + v[k].z + v[k].w;
    }
    red[t] = sum; __syncthreads();
    for (int s = 128; s > 0; s >>= 1) { if (t < s) red[t] += red[t+s]; __syncthreads(); }
    float inv = 1.f / red[0];
    #pragma unroll
    for (int k = 0; k < 4; k++) {
        v[k].x *= inv; v[k].y *= inv; v[k].z *= inv; v[k].w *= inv;
        p[t + 256*k] = v[k];
    }
}

// ---------------------------------------------------------------- K5: m_h += attn @ logmap0(demo_hyp)
// chunked over x; vals cached+scaled in smem; atomicAdd partials into g_m.
__global__ void __launch_bounds__(256) k5_mh(
    const float* __restrict__ dhyp, const float* __restrict__ attn)
{
    int b = blockIdx.y;                   // 4
    int chunk = blockIdx.x;               // 32 chunks of 128 x
    int t = threadIdx.x;                  // 256
    __shared__ __align__(16) float vals[128*DH_];   // 32 KB
    __shared__ float scale_s[128];
    int xb = chunk * 128;

    if (t < 128) {
        const float* vp = dhyp + (size_t)(b*NL_ + xb + t)*DH_;
        float n2 = 0.f;
        #pragma unroll
        for (int i = 0; i < DH_; i += 4) {
            float4 q = *(const float4*)(vp + i);
            n2 += q.x*q.x + q.y*q.y + q.z*q.z + q.w*q.w;
        }
        float n = fmaxf(sqrtf(n2), 1e-15f);
        float u = fminf(n, 1.f - 1e-5f);
        scale_s[t] = atanhf(u) / n;
    }
    __syncthreads();

    const float4* src = (const float4*)(dhyp + (size_t)(b*NL_ + xb)*DH_);
    float4* dst = (float4*)vals;
    for (int k = t; k < 128*DH_/4; k += 256) {
        float4 q = src[k];
        float s = scale_s[k >> 4];        // 16 float4 per row
        q.x *= s; q.y *= s; q.z *= s; q.w *= s;
        dst[k] = q;
    }
    __syncthreads();

    int p     = t & 63;                   // row pair idx -> rows 2p, 2p+1
    int dhalf = (t >> 6) & 1;
    int xh    = t >> 7;                   // x half (0/1)
    int r0 = 2*p, r1 = 2*p + 1;
    float acc0[32], acc1[32];
    #pragma unroll
    for (int i = 0; i < 32; i++) { acc0[i] = 0.f; acc1[i] = 0.f; }

    const float* a0 = attn + (size_t)(b*128 + r0)*NL_ + xb + xh*64;
    const float* a1 = attn + (size_t)(b*128 + r1)*NL_ + xb + xh*64;
    for (int x = 0; x < 64; x++) {
        float av0 = a0[x], av1 = a1[x];
        const float4* vv = (const float4*)(vals + (xh*64 + x)*DH_ + dhalf*32);
        #pragma unroll
        for (int i = 0; i < 8; i++) {
            float4 q = vv[i];
            acc0[4*i+0] += av0*q.x; acc0[4*i+1] += av0*q.y;
            acc0[4*i+2] += av0*q.z; acc0[4*i+3] += av0*q.w;
            acc1[4*i+0] += av1*q.x; acc1[4*i+1] += av1*q.y;
            acc1[4*i+2] += av1*q.z; acc1[4*i+3] += av1*q.w;
        }
    }
    float* m0 = g_m + (size_t)(b*128 + r0)*DH_ + dhalf*32;
    float* m1 = g_m + (size_t)(b*128 + r1)*DH_ + dhalf*32;
    #pragma unroll
    for (int i = 0; i < 32; i++) {
        atomicAdd(m0 + i, acc0[i]);
        atomicAdd(m1 + i, acc1[i]);
    }
}

// ---------------------------------------------------------------- K6: hyperbolic epilogue
__global__ void __launch_bounds__(64) k6_final(float* __restrict__ out)
{
    int ba = blockIdx.x;                  // 64 = b*16+a
    int b = ba >> 4, a = ba & 15;
    int t = threadIdx.x;                  // 64 = d
    __shared__ float red[64];

    float g = 0.f;
    for (int h = 0; h < H_; h++) {
        float m = g_m[(size_t)(b*128 + h*16 + a)*DH_ + t];
        red[t] = m*m; __syncthreads();
        for (int s = 32; s > 0; s >>= 1) { if (t < s) red[t] += red[t+s]; __syncthreads(); }
        float nm = fmaxf(sqrtf(red[0]), 1e-15f); __syncthreads();
        float e = tanhf(nm) * m / nm;
        red[t] = e*e; __syncthreads();
        for (int s = 32; s > 0; s >>= 1) { if (t < s) red[t] += red[t+s]; __syncthreads(); }
        float ne = fmaxf(sqrtf(red[0]), 1e-15f); __syncthreads();
        float u = fminf(ne, 1.f - 1e-5f);
        g += atanhf(u) * e / ne;
    }
    g *= (1.f/H_);
    red[t] = g*g; __syncthreads();
    for (int s = 32; s > 0; s >>= 1) { if (t < s) red[t] += red[t+s]; __syncthreads(); }
    float ng = fmaxf(sqrtf(red[0]), 1e-15f); __syncthreads();
    float ch = tanhf(ng) * g / ng;
    red[t] = ch*ch; __syncthreads();
    for (int s = 32; s > 0; s >>= 1) { if (t < s) red[t] += red[t+s]; __syncthreads(); }
    float norm = fmaxf(sqrtf(red[0]), 1e-6f);
    ch *= fminf((1.f - 1e-5f) / norm, 1.f);
    atomicAdd(out + b*DH_ + t, ch * (1.f/A_));
}

// ----------------------------------------------------------------
extern "C" void kernel_launch(void* const* d_in, const int* in_sizes, int n_in,
                              void* d_out, int out_size)
{
    const float* curr = (const float*)d_in[0];
    const float* demo = (const float*)d_in[1];
    const float* dhyp = (const float*)d_in[2];
    const int*   mask = (const int*)d_in[3];
    const float* Wq   = (const float*)d_in[4];
    const float* Wk   = (const float*)d_in[5];
    const float* lqw  = (const float*)d_in[6];
    const float* lqb  = (const float*)d_in[7];
    const float* lkw  = (const float*)d_in[8];
    const float* lkb  = (const float*)d_in[9];
    float* out  = (float*)d_out;
    float* attn = out + 256;

    k0_zero<<<129, 256>>>(out);
    k1_q<<<64, 256>>>(curr, Wq, lqw, lqb);
    k2_qw<<<512, 256>>>(Wk, lkw, lkb);
    dim3 g3(16, 64);
    k3_scores<<<g3, 256>>>(demo, mask, attn);
    k4_softmax<<<512, 256>>>(attn);
    dim3 g5(32, 4);
    k5_mh<<<g5, 256>>>(dhyp, attn);
    k6_final<<<64, 64>>>(out);
}

// round 3
// speedup vs baseline: 1.4463x; 1.4463x over previous
#include <cuda_runtime.h>
#include <math.h>

#define B_ 4
#define A_ 16
#define N_ 8
#define L_ 512
#define DE_ 256
#define DH_ 64
#define H_ 8
#define DHEAD_ 32
#define NL_ 4096
#define LN_EPS 1e-5f

typedef unsigned long long u64;

// Scratch (no cudaMalloc allowed)
__device__ __align__(16) float g_q[B_*A_*DE_];          // 64KB
__device__ __align__(16) float g_qWw[B_*A_*H_*DE_];     // 512KB
__device__ float g_S0[B_*A_*H_];
__device__ float g_S1[B_*A_*H_];
__device__ __align__(16) float g_m[B_*H_*A_*DH_];       // 128KB

// ---- packed f32x2 helpers (Blackwell FFMA2: PTX-only) ----
__device__ __forceinline__ u64 pk2(float lo, float hi) {
    u64 r; asm("mov.b64 %0, {%1, %2};" : "=l"(r) : "f"(lo), "f"(hi)); return r;
}
__device__ __forceinline__ void upk2(u64 v, float& lo, float& hi) {
    asm("mov.b64 {%0, %1}, %2;" : "=f"(lo), "=f"(hi) : "l"(v));
}
__device__ __forceinline__ u64 fma2(u64 a, u64 b, u64 c) {
    u64 d; asm("fma.rn.f32x2 %0, %1, %2, %3;" : "=l"(d) : "l"(a), "l"(b), "l"(c)); return d;
}
__device__ __forceinline__ u64 add2(u64 a, u64 b) {
    u64 d; asm("add.rn.f32x2 %0, %1, %2;" : "=l"(d) : "l"(a), "l"(b)); return d;
}

// ---------------------------------------------------------------- K0: zero
__global__ void k0_zero(float* __restrict__ out) {
    int i = blockIdx.x * blockDim.x + threadIdx.x;
    if (i < 256) out[i] = 0.f;
    if (i < B_*H_*A_*DH_) g_m[i] = 0.f;
}

// ---------------------------------------------------------------- K1: q = LN(curr) @ Wq.T
__global__ void __launch_bounds__(256) k1_q(
    const float* __restrict__ curr, const float* __restrict__ Wq,
    const float* __restrict__ lw, const float* __restrict__ lb)
{
    int ba = blockIdx.x;          // 0..63 = b*16+a
    int t  = threadIdx.x;         // 256
    __shared__ __align__(16) float xs[DE_];
    __shared__ float red[256];

    float x = curr[ba*DE_ + t];
    red[t] = x; __syncthreads();
    for (int s = 128; s > 0; s >>= 1) { if (t < s) red[t] += red[t+s]; __syncthreads(); }
    float mu = red[0] * (1.f/DE_);
    __syncthreads();
    red[t] = (x-mu)*(x-mu); __syncthreads();
    for (int s = 128; s > 0; s >>= 1) { if (t < s) red[t] += red[t+s]; __syncthreads(); }
    float rsd = rsqrtf(red[0] * (1.f/DE_) + LN_EPS);
    __syncthreads();
    xs[t] = (x - mu) * rsd * lw[t] + lb[t];
    __syncthreads();

    float acc = 0.f;
    const float* wr = Wq + t*DE_;
    #pragma unroll 8
    for (int i = 0; i < DE_; i += 4) {
        float4 xv = *(const float4*)(xs + i);
        float4 wv = *(const float4*)(wr + i);
        acc += xv.x*wv.x + xv.y*wv.y + xv.z*wv.z + xv.w*wv.w;
    }
    g_q[ba*DE_ + t] = acc;
}

// ---------------------------------------------------------------- K2: qWw, S0, S1
__global__ void __launch_bounds__(256) k2_qw(
    const float* __restrict__ Wk, const float* __restrict__ lkw,
    const float* __restrict__ lkb)
{
    int bah = blockIdx.x;         // (b*16+a)*8 + h
    int h   = bah & 7;
    int ba  = bah >> 3;
    int t   = threadIdx.x;
    __shared__ float qs[DHEAD_];
    __shared__ float red[256];

    if (t < DHEAD_) qs[t] = g_q[ba*DE_ + h*DHEAD_ + t];
    __syncthreads();

    float acc = 0.f;
    #pragma unroll
    for (int d = 0; d < DHEAD_; d++)
        acc += qs[d] * Wk[(h*DHEAD_ + d)*DE_ + t];

    const float sc = 0.1767766952966369f;   // 1/sqrt(32)
    float qww = acc * lkw[t] * sc;
    float s0c = acc * lkb[t] * sc;
    g_qWw[bah*DE_ + t] = qww;

    red[t] = qww; __syncthreads();
    for (int s = 128; s > 0; s >>= 1) { if (t < s) red[t] += red[t+s]; __syncthreads(); }
    if (t == 0) g_S1[bah] = red[0];
    __syncthreads();
    red[t] = s0c; __syncthreads();
    for (int s = 128; s > 0; s >>= 1) { if (t < s) red[t] += red[t+s]; __syncthreads(); }
    if (t == 0) g_S0[bah] = red[0];
}

// ---------------------------------------------------------------- K3: fused LN+proj scores
// thread-per-row: each thread owns one x-row; accumulators in registers,
// coefficients broadcast from smem, packed f32x2 FMA. No shuffles, no syncs.
__global__ void __launch_bounds__(256) k3_scores(
    const float* __restrict__ demo, const int* __restrict__ mask,
    float* __restrict__ attn)
{
    int ba    = blockIdx.y;               // 64
    int chunk = blockIdx.x;               // 16 chunks of 256 rows
    int b = ba >> 4, a = ba & 15;
    int t = threadIdx.x;

    __shared__ __align__(16) float4 cs[H_][DE_/4];   // 8KB coefficients
    __shared__ float S0s[H_], S1s[H_];

    for (int k = t; k < H_*DE_/4; k += 256) {
        int h = k >> 6, i4 = k & 63;
        cs[h][i4] = ((const float4*)(g_qWw + (size_t)(ba*H_ + h)*DE_))[i4];
    }
    if (t < H_) { S1s[t] = g_S1[ba*H_+t]; S0s[t] = g_S0[ba*H_+t]; }
    __syncthreads();

    int x = chunk*256 + t;
    const float4* xp = (const float4*)(demo + (size_t)(b*NL_ + x)*(A_*DE_) + a*DE_);

    u64 sum = 0ull, ssq = 0ull;
    u64 dot[H_];
    #pragma unroll
    for (int h = 0; h < H_; h++) dot[h] = 0ull;

    #pragma unroll 8
    for (int i4 = 0; i4 < DE_/4; i4++) {
        float4 xv = xp[i4];
        u64 xlo = pk2(xv.x, xv.y);
        u64 xhi = pk2(xv.z, xv.w);
        sum = add2(sum, xlo);
        sum = add2(sum, xhi);
        ssq = fma2(xlo, xlo, ssq);
        ssq = fma2(xhi, xhi, ssq);
        #pragma unroll
        for (int h = 0; h < H_; h++) {
            float4 cv = cs[h][i4];
            u64 clo = pk2(cv.x, cv.y);
            u64 chi = pk2(cv.z, cv.w);
            dot[h] = fma2(clo, xlo, dot[h]);
            dot[h] = fma2(chi, xhi, dot[h]);
        }
    }

    float slo, shi; upk2(sum, slo, shi);
    float qlo, qhi; upk2(ssq, qlo, qhi);
    float sumf = slo + shi;
    float ssqf = qlo + qhi;
    float mu  = sumf * (1.f/256.f);
    float var = ssqf * (1.f/256.f) - mu*mu;
    float rsd = rsqrtf(var + LN_EPS);
    int   mk  = mask[b*NL_ + x];

    #pragma unroll
    for (int h = 0; h < H_; h++) {
        float dlo, dhi; upk2(dot[h], dlo, dhi);
        float df = dlo + dhi;
        float sc = (df - mu*S1s[h]) * rsd + S0s[h];
        attn[((size_t)(b*H_+h)*A_ + a)*NL_ + x] = mk ? sc : -INFINITY;
    }
}

// ---------------------------------------------------------------- K4: softmax in-place over NL
__global__ void __launch_bounds__(256) k4_softmax(float* __restrict__ attn)
{
    int row = blockIdx.x;                 // 512 = b*H*A
    float4* p = (float4*)(attn + (size_t)row*NL_);
    int t = threadIdx.x;
    __shared__ float red[256];

    float4 v[4];
    float mx = -INFINITY;
    #pragma unroll
    for (int k = 0; k < 4; k++) {
        v[k] = p[t + 256*k];
        mx = fmaxf(mx, fmaxf(fmaxf(v[k].x, v[k].y), fmaxf(v[k].z, v[k].w)));
    }
    red[t] = mx; __syncthreads();
    for (int s = 128; s > 0; s >>= 1) { if (t < s) red[t] = fmaxf(red[t], red[t+s]); __syncthreads(); }
    mx = red[0]; __syncthreads();

    float sum = 0.f;
    #pragma unroll
    for (int k = 0; k < 4; k++) {
        v[k].x = __expf(v[k].x - mx); v[k].y = __expf(v[k].y - mx);
        v[k].z = __expf(v[k].z - mx); v[k].w = __expf(v[k].w - mx);
        sum += v[k].x + v[k].y + v[k].z + v[k].w;
    }
    red[t] = sum; __syncthreads();
    for (int s = 128; s > 0; s >>= 1) { if (t < s) red[t] += red[t+s]; __syncthreads(); }
    float inv = 1.f / red[0];
    #pragma unroll
    for (int k = 0; k < 4; k++) {
        v[k].x *= inv; v[k].y *= inv; v[k].z *= inv; v[k].w *= inv;
        p[t + 256*k] = v[k];
    }
}

// ---------------------------------------------------------------- K5: m_h += attn @ logmap0(demo_hyp)
__global__ void __launch_bounds__(256) k5_mh(
    const float* __restrict__ dhyp, const float* __restrict__ attn)
{
    int b = blockIdx.y;                   // 4
    int chunk = blockIdx.x;               // 32 chunks of 128 x
    int t = threadIdx.x;                  // 256
    __shared__ __align__(16) float vals[128*DH_];   // 32 KB
    __shared__ float scale_s[128];
    int xb = chunk * 128;

    if (t < 128) {
        const float* vp = dhyp + (size_t)(b*NL_ + xb + t)*DH_;
        float n2 = 0.f;
        #pragma unroll
        for (int i = 0; i < DH_; i += 4) {
            float4 q = *(const float4*)(vp + i);
            n2 += q.x*q.x + q.y*q.y + q.z*q.z + q.w*q.w;
        }
        float n = fmaxf(sqrtf(n2), 1e-15f);
        float u = fminf(n, 1.f - 1e-5f);
        scale_s[t] = atanhf(u) / n;
    }
    __syncthreads();

    const float4* src = (const float4*)(dhyp + (size_t)(b*NL_ + xb)*DH_);
    float4* dst = (float4*)vals;
    for (int k = t; k < 128*DH_/4; k += 256) {
        float4 q = src[k];
        float s = scale_s[k >> 4];        // 16 float4 per row
        q.x *= s; q.y *= s; q.z *= s; q.w *= s;
        dst[k] = q;
    }
    __syncthreads();

    int p     = t & 63;                   // row pair idx -> rows 2p, 2p+1
    int dhalf = (t >> 6) & 1;
    int xh    = t >> 7;                   // x half (0/1)
    int r0 = 2*p, r1 = 2*p + 1;
    float acc0[32], acc1[32];
    #pragma unroll
    for (int i = 0; i < 32; i++) { acc0[i] = 0.f; acc1[i] = 0.f; }

    const float4* a0 = (const float4*)(attn + (size_t)(b*128 + r0)*NL_ + xb + xh*64);
    const float4* a1 = (const float4*)(attn + (size_t)(b*128 + r1)*NL_ + xb + xh*64);
    for (int x4 = 0; x4 < 16; x4++) {
        float4 av0 = a0[x4];
        float4 av1 = a1[x4];
        #pragma unroll
        for (int xx = 0; xx < 4; xx++) {
            float w0 = (&av0.x)[xx];
            float w1 = (&av1.x)[xx];
            const float4* vv = (const float4*)(vals + (xh*64 + x4*4 + xx)*DH_ + dhalf*32);
            #pragma unroll
            for (int i = 0; i < 8; i++) {
                float4 q = vv[i];
                acc0[4*i+0] += w0*q.x; acc0[4*i+1] += w0*q.y;
                acc0[4*i+2] += w0*q.z; acc0[4*i+3] += w0*q.w;
                acc1[4*i+0] += w1*q.x; acc1[4*i+1] += w1*q.y;
                acc1[4*i+2] += w1*q.z; acc1[4*i+3] += w1*q.w;
            }
        }
    }
    float* m0 = g_m + (size_t)(b*128 + r0)*DH_ + dhalf*32;
    float* m1 = g_m + (size_t)(b*128 + r1)*DH_ + dhalf*32;
    #pragma unroll
    for (int i = 0; i < 32; i++) {
        atomicAdd(m0 + i, acc0[i]);
        atomicAdd(m1 + i, acc1[i]);
    }
}

// ---------------------------------------------------------------- K6: hyperbolic epilogue
__global__ void __launch_bounds__(64) k6_final(float* __restrict__ out)
{
    int ba = blockIdx.x;                  // 64 = b*16+a
    int b = ba >> 4, a = ba & 15;
    int t = threadIdx.x;                  // 64 = d
    __shared__ float red[64];

    float g = 0.f;
    for (int h = 0; h < H_; h++) {
        float m = g_m[(size_t)(b*128 + h*16 + a)*DH_ + t];
        red[t] = m*m; __syncthreads();
        for (int s = 32; s > 0; s >>= 1) { if (t < s) red[t] += red[t+s]; __syncthreads(); }
        float nm = fmaxf(sqrtf(red[0]), 1e-15f); __syncthreads();
        float e = tanhf(nm) * m / nm;
        red[t] = e*e; __syncthreads();
        for (int s = 32; s > 0; s >>= 1) { if (t < s) red[t] += red[t+s]; __syncthreads(); }
        float ne = fmaxf(sqrtf(red[0]), 1e-15f); __syncthreads();
        float u = fminf(ne, 1.f - 1e-5f);
        g += atanhf(u) * e / ne;
    }
    g *= (1.f/H_);
    red[t] = g*g; __syncthreads();
    for (int s = 32; s > 0; s >>= 1) { if (t < s) red[t] += red[t+s]; __syncthreads(); }
    float ng = fmaxf(sqrtf(red[0]), 1e-15f); __syncthreads();
    float ch = tanhf(ng) * g / ng;
    red[t] = ch*ch; __syncthreads();
    for (int s = 32; s > 0; s >>= 1) { if (t < s) red[t] += red[t+s]; __syncthreads(); }
    float norm = fmaxf(sqrtf(red[0]), 1e-6f);
    ch *= fminf((1.f - 1e-5f) / norm, 1.f);
    atomicAdd(out + b*DH_ + t, ch * (1.f/A_));
}

// ----------------------------------------------------------------
extern "C" void kernel_launch(void* const* d_in, const int* in_sizes, int n_in,
                              void* d_out, int out_size)
{
    const float* curr = (const float*)d_in[0];
    const float* demo = (const float*)d_in[1];
    const float* dhyp = (const float*)d_in[2];
    const int*   mask = (const int*)d_in[3];
    const float* Wq   = (const float*)d_in[4];
    const float* Wk   = (const float*)d_in[5];
    const float* lqw  = (const float*)d_in[6];
    const float* lqb  = (const float*)d_in[7];
    const float* lkw  = (const float*)d_in[8];
    const float* lkb  = (const float*)d_in[9];
    float* out  = (float*)d_out;
    float* attn = out + 256;

    k0_zero<<<129, 256>>>(out);
    k1_q<<<64, 256>>>(curr, Wq, lqw, lqb);
    k2_qw<<<512, 256>>>(Wk, lkw, lkb);
    dim3 g3(16, 64);
    k3_scores<<<g3, 256>>>(demo, mask, attn);
    k4_softmax<<<512, 256>>>(attn);
    dim3 g5(32, 4);
    k5_mh<<<g5, 256>>>(dhyp, attn);
    k6_final<<<64, 64>>>(out);
}

// round 4
// speedup vs baseline: 1.5568x; 1.0764x over previous
#include <cuda_runtime.h>
#include <math.h>

#define B_ 4
#define A_ 16
#define N_ 8
#define L_ 512
#define DE_ 256
#define DH_ 64
#define H_ 8
#define DHEAD_ 32
#define NL_ 4096
#define LN_EPS 1e-5f

typedef unsigned long long u64;

// Scratch (no cudaMalloc allowed)
__device__ __align__(16) float g_qWw[B_*A_*H_*DE_];     // 512KB
__device__ float g_S0[B_*A_*H_];
__device__ float g_S1[B_*A_*H_];
__device__ __align__(16) float g_m[B_*H_*A_*DH_];       // 128KB

// ---- packed f32x2 helpers ----
__device__ __forceinline__ u64 pk2(float lo, float hi) {
    u64 r; asm("mov.b64 %0, {%1, %2};" : "=l"(r) : "f"(lo), "f"(hi)); return r;
}
__device__ __forceinline__ void upk2(u64 v, float& lo, float& hi) {
    asm("mov.b64 {%0, %1}, %2;" : "=f"(lo), "=f"(hi) : "l"(v));
}
__device__ __forceinline__ u64 fma2(u64 a, u64 b, u64 c) {
    u64 d; asm("fma.rn.f32x2 %0, %1, %2, %3;" : "=l"(d) : "l"(a), "l"(b), "l"(c)); return d;
}
__device__ __forceinline__ u64 add2(u64 a, u64 b) {
    u64 d; asm("add.rn.f32x2 %0, %1, %2;" : "=l"(d) : "l"(a), "l"(b)); return d;
}
__device__ __forceinline__ float upksum(u64 v) {
    float lo, hi; upk2(v, lo, hi); return lo + hi;
}
// sum across 8-lane group (offsets 1,2,4)
__device__ __forceinline__ float grp8_sum(float v) {
    v += __shfl_xor_sync(0xffffffffu, v, 1);
    v += __shfl_xor_sync(0xffffffffu, v, 2);
    v += __shfl_xor_sync(0xffffffffu, v, 4);
    return v;
}
// full-warp sum
__device__ __forceinline__ float warp_sum(float v) {
    #pragma unroll
    for (int o = 16; o > 0; o >>= 1) v += __shfl_xor_sync(0xffffffffu, v, o);
    return v;
}

// ---------------------------------------------------------------- K0: zero
__global__ void k0_zero(float* __restrict__ out) {
    int i = blockIdx.x * blockDim.x + threadIdx.x;
    if (i < 256) out[i] = 0.f;
    if (i < B_*H_*A_*DH_) g_m[i] = 0.f;
    if (i < B_*A_*H_) { g_S0[i] = 0.f; g_S1[i] = 0.f; }
}

// ---------------------------------------------------------------- K12: q = LN(curr)@Wq.T, then qWw/S0/S1
__global__ void __launch_bounds__(256) k12_prep(
    const float* __restrict__ curr, const float* __restrict__ Wq,
    const float* __restrict__ Wk,
    const float* __restrict__ lqw, const float* __restrict__ lqb,
    const float* __restrict__ lkw, const float* __restrict__ lkb)
{
    int ba = blockIdx.x;          // 0..63
    int t  = threadIdx.x;         // 256
    int lane = t & 31;
    __shared__ __align__(16) float xs[DE_];
    __shared__ float red[256];
    __shared__ __align__(16) float qv[DE_];

    float x = curr[ba*DE_ + t];
    red[t] = x; __syncthreads();
    for (int s = 128; s > 0; s >>= 1) { if (t < s) red[t] += red[t+s]; __syncthreads(); }
    float mu = red[0] * (1.f/DE_);
    __syncthreads();
    red[t] = (x-mu)*(x-mu); __syncthreads();
    for (int s = 128; s > 0; s >>= 1) { if (t < s) red[t] += red[t+s]; __syncthreads(); }
    float rsd = rsqrtf(red[0] * (1.f/DE_) + LN_EPS);
    __syncthreads();
    xs[t] = (x - mu) * rsd * lqw[t] + lqb[t];
    __syncthreads();

    float acc = 0.f;
    const float* wr = Wq + t*DE_;
    #pragma unroll 8
    for (int i = 0; i < DE_; i += 4) {
        float4 xv = *(const float4*)(xs + i);
        float4 wv = *(const float4*)(wr + i);
        acc += xv.x*wv.x + xv.y*wv.y + xv.z*wv.z + xv.w*wv.w;
    }
    qv[t] = acc;
    __syncthreads();

    const float sc = 0.1767766952966369f;   // 1/sqrt(32)
    float wkt = lkw[t], bkt = lkb[t];
    #pragma unroll
    for (int h = 0; h < H_; h++) {
        float a2 = 0.f;
        #pragma unroll 8
        for (int d = 0; d < DHEAD_; d++)
            a2 += qv[h*DHEAD_ + d] * Wk[(h*DHEAD_ + d)*DE_ + t];
        float qww = a2 * wkt * sc;
        float s0c = a2 * bkt * sc;
        g_qWw[(size_t)(ba*H_ + h)*DE_ + t] = qww;
        float r1 = warp_sum(qww);
        float r0 = warp_sum(s0c);
        if (lane == 0) {
            atomicAdd(&g_S1[ba*H_+h], r1);
            atomicAdd(&g_S0[ba*H_+h], r0);
        }
    }
}

// ---------------------------------------------------------------- K3: fused LN+proj scores
// 8 lanes per row (G=8): coalesced LDG, 3-stage group reductions.
// warp handles 8 rows per pass (4 lane-groups x 2 rows), 4 passes -> 32 rows.
__global__ void __launch_bounds__(256) k3_scores(
    const float* __restrict__ demo, const int* __restrict__ mask,
    float* __restrict__ attn)
{
    int ba    = blockIdx.y;               // 64
    int chunk = blockIdx.x;               // 16 chunks of 256 rows
    int b = ba >> 4, a = ba & 15;
    int t = threadIdx.x;
    int warp = t >> 5, lane = t & 31;
    int g  = lane & 7;                    // element-slice within row
    int r4 = lane >> 3;                   // row-group 0..3

    __shared__ __align__(16) float4 cs[H_][DE_/4];   // 8KB coefficients
    __shared__ float S0s[H_], S1s[H_];

    for (int k = t; k < H_*DE_/4; k += 256) {
        int h = k >> 6, i4 = k & 63;
        cs[h][i4] = ((const float4*)(g_qWw + (size_t)(ba*H_ + h)*DE_))[i4];
    }
    if (t < H_) { S1s[t] = g_S1[ba*H_+t]; S0s[t] = g_S0[ba*H_+t]; }
    __syncthreads();

    int base = chunk*256 + warp*32;
    #pragma unroll 1
    for (int pass = 0; pass < 4; pass++) {
        int xr0 = base + pass*8 + r4*2;   // this lane-group's rows
        int xr1 = xr0 + 1;
        const float4* p0 = (const float4*)(demo + ((size_t)(b*NL_ + xr0)*A_ + a)*DE_);
        const float4* p1 = p0 + (A_*DE_/4);   // next x row

        u64 sum0 = 0, ssq0 = 0, sum1 = 0, ssq1 = 0;
        u64 dot0[H_], dot1[H_];
        #pragma unroll
        for (int h = 0; h < H_; h++) { dot0[h] = 0; dot1[h] = 0; }

        #pragma unroll
        for (int i = 0; i < 8; i++) {
            float4 xa = __ldcs(p0 + i*8 + g);
            float4 xb = __ldcs(p1 + i*8 + g);
            u64 xa0 = pk2(xa.x, xa.y), xa1 = pk2(xa.z, xa.w);
            u64 xb0 = pk2(xb.x, xb.y), xb1 = pk2(xb.z, xb.w);
            sum0 = add2(sum0, xa0); sum0 = add2(sum0, xa1);
            ssq0 = fma2(xa0, xa0, ssq0); ssq0 = fma2(xa1, xa1, ssq0);
            sum1 = add2(sum1, xb0); sum1 = add2(sum1, xb1);
            ssq1 = fma2(xb0, xb0, ssq1); ssq1 = fma2(xb1, xb1, ssq1);
            #pragma unroll
            for (int h = 0; h < H_; h++) {
                float4 cv = cs[h][i*8 + g];
                u64 c0 = pk2(cv.x, cv.y), c1 = pk2(cv.z, cv.w);
                dot0[h] = fma2(c0, xa0, dot0[h]); dot0[h] = fma2(c1, xa1, dot0[h]);
                dot1[h] = fma2(c0, xb0, dot1[h]); dot1[h] = fma2(c1, xb1, dot1[h]);
            }
        }

        // reduce within 8-lane groups (one shfl covers all 4 groups)
        float s0 = grp8_sum(upksum(sum0));
        float q0 = grp8_sum(upksum(ssq0));
        float s1 = grp8_sum(upksum(sum1));
        float q1 = grp8_sum(upksum(ssq1));
        float d0[H_], d1[H_];
        #pragma unroll
        for (int h = 0; h < H_; h++) {
            d0[h] = grp8_sum(upksum(dot0[h]));
            d1[h] = grp8_sum(upksum(dot1[h]));
        }

        float mu0  = s0 * (1.f/256.f);
        float rsd0 = rsqrtf(q0 * (1.f/256.f) - mu0*mu0 + LN_EPS);
        float mu1  = s1 * (1.f/256.f);
        float rsd1 = rsqrtf(q1 * (1.f/256.f) - mu1*mu1 + LN_EPS);
        int mk0 = mask[b*NL_ + xr0];
        int mk1 = mask[b*NL_ + xr1];

        #pragma unroll
        for (int h = 0; h < H_; h++) {
            if (g == h) {
                float sc0 = (d0[h] - mu0*S1s[h]) * rsd0 + S0s[h];
                float sc1 = (d1[h] - mu1*S1s[h]) * rsd1 + S0s[h];
                size_t rb = ((size_t)(b*H_+h)*A_ + a)*NL_;
                attn[rb + xr0] = mk0 ? sc0 : -INFINITY;
                attn[rb + xr1] = mk1 ? sc1 : -INFINITY;
            }
        }
    }
}

// ---------------------------------------------------------------- K4: softmax in-place over NL
__global__ void __launch_bounds__(256) k4_softmax(float* __restrict__ attn)
{
    int row = blockIdx.x;                 // 512 = b*H*A
    float4* p = (float4*)(attn + (size_t)row*NL_);
    int t = threadIdx.x;
    __shared__ float red[256];

    float4 v[4];
    float mx = -INFINITY;
    #pragma unroll
    for (int k = 0; k < 4; k++) {
        v[k] = p[t + 256*k];
        mx = fmaxf(mx, fmaxf(fmaxf(v[k].x, v[k].y), fmaxf(v[k].z, v[k].w)));
    }
    red[t] = mx; __syncthreads();
    for (int s = 128; s > 0; s >>= 1) { if (t < s) red[t] = fmaxf(red[t], red[t+s]); __syncthreads(); }
    mx = red[0]; __syncthreads();

    float sum = 0.f;
    #pragma unroll
    for (int k = 0; k < 4; k++) {
        v[k].x = __expf(v[k].x - mx); v[k].y = __expf(v[k].y - mx);
        v[k].z = __expf(v[k].z - mx); v[k].w = __expf(v[k].w - mx);
        sum += v[k].x + v[k].y + v[k].z + v[k].w;
    }
    red[t] = sum; __syncthreads();
    for (int s = 128; s > 0; s >>= 1) { if (t < s) red[t] += red[t+s]; __syncthreads(); }
    float inv = 1.f / red[0];
    #pragma unroll
    for (int k = 0; k < 4; k++) {
        v[k].x *= inv; v[k].y *= inv; v[k].z *= inv; v[k].w *= inv;
        p[t + 256*k] = v[k];
    }
}

// ---------------------------------------------------------------- K5: m_h += attn @ logmap0(demo_hyp)
// grid (64 x-chunks, 4 b); block 256: thread = (row 0..127, dhalf)
__global__ void __launch_bounds__(256) k5_mh(
    const float* __restrict__ dhyp, const float* __restrict__ attn)
{
    int b = blockIdx.y;
    int chunk = blockIdx.x;               // 64 chunks of 64 x
    int t = threadIdx.x;
    __shared__ __align__(16) float vals[64*DH_];    // 16KB
    __shared__ float scale_s[64];
    int xb = chunk * 64;

    if (t < 64) {
        const float* vp = dhyp + (size_t)(b*NL_ + xb + t)*DH_;
        float n2 = 0.f;
        #pragma unroll
        for (int i = 0; i < DH_; i += 4) {
            float4 q = *(const float4*)(vp + i);
            n2 += q.x*q.x + q.y*q.y + q.z*q.z + q.w*q.w;
        }
        float n = fmaxf(sqrtf(n2), 1e-15f);
        float u = fminf(n, 1.f - 1e-5f);
        scale_s[t] = atanhf(u) / n;
    }
    __syncthreads();

    const float4* src = (const float4*)(dhyp + (size_t)(b*NL_ + xb)*DH_);
    float4* dst = (float4*)vals;
    #pragma unroll
    for (int j = 0; j < 4; j++) {
        int k = t + 256*j;                // 1024 float4
        float4 q = src[k];
        float s = scale_s[k >> 4];
        q.x *= s; q.y *= s; q.z *= s; q.w *= s;
        dst[k] = q;
    }
    __syncthreads();

    int row   = t & 127;
    int dhalf = t >> 7;
    u64 acc[16];
    #pragma unroll
    for (int i = 0; i < 16; i++) acc[i] = 0;

    const float4* arow = (const float4*)(attn + ((size_t)(b*128 + row)*NL_ + xb));
    #pragma unroll 4
    for (int x4 = 0; x4 < 16; x4++) {
        float4 w = arow[x4];
        #pragma unroll
        for (int xx = 0; xx < 4; xx++) {
            float wv = (&w.x)[xx];
            u64 w2 = pk2(wv, wv);
            const float4* vv = (const float4*)(vals + (x4*4 + xx)*DH_ + dhalf*32);
            #pragma unroll
            for (int i = 0; i < 8; i++) {
                float4 q = vv[i];
                acc[2*i+0] = fma2(pk2(q.x, q.y), w2, acc[2*i+0]);
                acc[2*i+1] = fma2(pk2(q.z, q.w), w2, acc[2*i+1]);
            }
        }
    }
    float* m0 = g_m + (size_t)(b*128 + row)*DH_ + dhalf*32;
    #pragma unroll
    for (int i = 0; i < 16; i++) {
        float lo, hi; upk2(acc[i], lo, hi);
        atomicAdd(m0 + 2*i,     lo);
        atomicAdd(m0 + 2*i + 1, hi);
    }
}

// ---------------------------------------------------------------- K6: hyperbolic epilogue (warp per ba)
__global__ void __launch_bounds__(32) k6_final(float* __restrict__ out)
{
    int ba = blockIdx.x;                  // 64 = b*16+a
    int b = ba >> 4, a = ba & 15;
    int lane = threadIdx.x;               // 32; holds d=lane, d=lane+32

    float g0 = 0.f, g1 = 0.f;
    #pragma unroll 1
    for (int h = 0; h < H_; h++) {
        const float* mp = g_m + (size_t)(b*128 + h*16 + a)*DH_;
        float m0 = mp[lane], m1 = mp[lane+32];
        float nm = fmaxf(sqrtf(warp_sum(m0*m0 + m1*m1)), 1e-15f);
        float th = tanhf(nm) / nm;
        float e0 = th*m0, e1 = th*m1;
        float ne = fmaxf(sqrtf(warp_sum(e0*e0 + e1*e1)), 1e-15f);
        float u = fminf(ne, 1.f - 1e-5f);
        float at = atanhf(u) / ne;
        g0 += at*e0; g1 += at*e1;
    }
    g0 *= (1.f/H_); g1 *= (1.f/H_);
    float ng = fmaxf(sqrtf(warp_sum(g0*g0 + g1*g1)), 1e-15f);
    float th = tanhf(ng) / ng;
    float c0 = th*g0, c1 = th*g1;
    float norm = fmaxf(sqrtf(warp_sum(c0*c0 + c1*c1)), 1e-6f);
    float s = fminf((1.f - 1e-5f) / norm, 1.f) * (1.f/A_);
    atomicAdd(out + b*DH_ + lane,      c0 * s);
    atomicAdd(out + b*DH_ + lane + 32, c1 * s);
}

// ----------------------------------------------------------------
extern "C" void kernel_launch(void* const* d_in, const int* in_sizes, int n_in,
                              void* d_out, int out_size)
{
    const float* curr = (const float*)d_in[0];
    const float* demo = (const float*)d_in[1];
    const float* dhyp = (const float*)d_in[2];
    const int*   mask = (const int*)d_in[3];
    const float* Wq   = (const float*)d_in[4];
    const float* Wk   = (const float*)d_in[5];
    const float* lqw  = (const float*)d_in[6];
    const float* lqb  = (const float*)d_in[7];
    const float* lkw  = (const float*)d_in[8];
    const float* lkb  = (const float*)d_in[9];
    float* out  = (float*)d_out;
    float* attn = out + 256;

    k0_zero<<<128, 256>>>(out);
    k12_prep<<<64, 256>>>(curr, Wq, Wk, lqw, lqb, lkw, lkb);
    dim3 g3(16, 64);
    k3_scores<<<g3, 256>>>(demo, mask, attn);
    k4_softmax<<<512, 256>>>(attn);
    dim3 g5(64, 4);
    k5_mh<<<g5, 256>>>(dhyp, attn);
    k6_final<<<64, 32>>>(out);
}